// round 6
// baseline (speedup 1.0000x reference)
#include <cuda_runtime.h>
#include <cuda_fp16.h>
#include <cstdint>
#include <cstddef>

#define NN 50000
#define DD 128
#define BM 128
#define ST 36            // smem row stride (words): conflict-free fragment access
#define PADN 53248       // 13 * 4096, >= NN, int4-aligned scan coverage
#define RSN (NN + 1)
#define NE 500000

// ---- Scratch (allocation-free rule: device globals) ----
__device__ float  g_Wh_elec[NN * DD];          // fp32 (needed exactly for K4 extra)
__device__ __half g_Wh16[2 * NN * DD];         // fp16 copies for gather (chem, elec)
__device__ float  g_h[NN * DD];
__device__ __align__(16) int g_deg[2 * PADN];  // per-etype dst degree (memset 0 each call)
__device__ int    g_rs[2 * RSN];               // CSR row starts
__device__ int    g_cur[2 * NN];               // placement cursors
__device__ int    g_csr[2 * NE];               // CSR src lists

__device__ __forceinline__ uint32_t f2tf32(float f) {
    uint32_t r;
    asm("cvt.rna.tf32.f32 %0, %1;" : "=r"(r) : "f"(f));
    return r;
}

__device__ __forceinline__ void mma_tf32(float c[4], const uint32_t a[4], const uint32_t b[2]) {
    asm volatile(
        "mma.sync.aligned.m16n8k8.row.col.f32.tf32.tf32.f32 "
        "{%0,%1,%2,%3}, {%4,%5,%6,%7}, {%8,%9}, {%0,%1,%2,%3};"
        : "+f"(c[0]), "+f"(c[1]), "+f"(c[2]), "+f"(c[3])
        : "r"(a[0]), "r"(a[1]), "r"(a[2]), "r"(a[3]), "r"(b[0]), "r"(b[1]));
}

// Dynamic smem: As[2][128][ST] | Ws[4][128][ST]
#define AS_WORDS (2 * 128 * ST)
#define WS_WORDS (4 * 128 * ST)
#define SMEM_BYTES ((AS_WORDS + WS_WORDS) * 4)

// C[M,128] = A[M,128] @ W^T + bias (+ extra). blockIdx.y selects param set.
// C may be null (skip fp32 store); C16, if set, receives an fp16 copy (bias included).
__global__ __launch_bounds__(256, 2)
void gemm_tf32_kernel(const float* __restrict__ A,
                      const float* __restrict__ W0, const float* __restrict__ b0,
                      float* __restrict__ C0, __half* __restrict__ C16_0,
                      const float* __restrict__ W1, const float* __restrict__ b1,
                      float* __restrict__ C1, __half* __restrict__ C16_1,
                      const float* __restrict__ extra,
                      int M)
{
    extern __shared__ uint32_t smem[];
    uint32_t* As = smem;
    uint32_t* Ws = smem + AS_WORDS;

    const float* W    = W0;
    const float* bias = b0;
    float*       C    = C0;
    __half*      C16  = C16_0;
    const float* ex   = extra;
    if (blockIdx.y == 1) { W = W1; bias = b1; C = C1; C16 = C16_1; ex = nullptr; }

    const int tid  = threadIdx.x;
    const int lane = tid & 31;
    const int w    = tid >> 5;
    const int wm   = w & 3;
    const int wn   = w >> 2;
    const int mw   = wm * 32;
    const int nw   = wn * 64;
    const int gid  = lane >> 2;
    const int tig  = lane & 3;
    const int bm   = blockIdx.x * BM;

    // Prologue: all of W (128x128) into Ws, tf32, row-major
    #pragma unroll
    for (int i = 0; i < 16; i++) {
        int g   = tid + 256 * i;
        int c   = g >> 10;
        int row = (g >> 3) & 127;
        int qc  = g & 7;
        float4 vb = *(const float4*)(W + (size_t)row * DD + c * 32 + qc * 4);
        uint4 sv;
        sv.x = f2tf32(vb.x); sv.y = f2tf32(vb.y);
        sv.z = f2tf32(vb.z); sv.w = f2tf32(vb.w);
        *(uint4*)&Ws[(size_t)c * 128 * ST + row * ST + qc * 4] = sv;
    }

    float4 av[4];
    #pragma unroll
    for (int i = 0; i < 4; i++) {
        int g = tid + 256 * i, row = g >> 3, qc = g & 7, ar = bm + row;
        av[i] = make_float4(0.f, 0.f, 0.f, 0.f);
        if (ar < M) av[i] = *(const float4*)(A + (size_t)ar * DD + qc * 4);
    }
    #pragma unroll
    for (int i = 0; i < 4; i++) {
        int g = tid + 256 * i, row = g >> 3, qc = g & 7;
        uint4 sv;
        sv.x = f2tf32(av[i].x); sv.y = f2tf32(av[i].y);
        sv.z = f2tf32(av[i].z); sv.w = f2tf32(av[i].w);
        *(uint4*)&As[row * ST + qc * 4] = sv;
    }
    __syncthreads();

    float acc[2][8][4];
    #pragma unroll
    for (int mt = 0; mt < 2; mt++)
        #pragma unroll
        for (int nt = 0; nt < 8; nt++)
            #pragma unroll
            for (int q = 0; q < 4; q++) acc[mt][nt][q] = 0.0f;

    #pragma unroll
    for (int c = 0; c < 4; c++) {
        if (c < 3) {
            #pragma unroll
            for (int i = 0; i < 4; i++) {
                int g = tid + 256 * i, row = g >> 3, qc = g & 7, ar = bm + row;
                av[i] = make_float4(0.f, 0.f, 0.f, 0.f);
                if (ar < M) av[i] = *(const float4*)(A + (size_t)ar * DD + (c + 1) * 32 + qc * 4);
            }
        }
        const uint32_t* Ab = As + (size_t)(c & 1) * 128 * ST;
        const uint32_t* Wc = Ws + (size_t)c * 128 * ST;
        #pragma unroll
        for (int ks = 0; ks < 4; ks++) {
            const int k8 = ks * 8;
            uint32_t a[2][4], b[8][2];
            #pragma unroll
            for (int mt = 0; mt < 2; mt++) {
                int r0 = mw + mt * 16 + gid;
                a[mt][0] = Ab[r0 * ST + k8 + tig];
                a[mt][1] = Ab[(r0 + 8) * ST + k8 + tig];
                a[mt][2] = Ab[r0 * ST + k8 + tig + 4];
                a[mt][3] = Ab[(r0 + 8) * ST + k8 + tig + 4];
            }
            #pragma unroll
            for (int nt = 0; nt < 8; nt++) {
                int cc = nw + nt * 8 + gid;
                b[nt][0] = Wc[cc * ST + k8 + tig];
                b[nt][1] = Wc[cc * ST + k8 + tig + 4];
            }
            #pragma unroll
            for (int mt = 0; mt < 2; mt++)
                #pragma unroll
                for (int nt = 0; nt < 8; nt++)
                    mma_tf32(acc[mt][nt], a[mt], b[nt]);
        }
        if (c < 3) {
            uint32_t* Anext = As + (size_t)((c + 1) & 1) * 128 * ST;
            #pragma unroll
            for (int i = 0; i < 4; i++) {
                int g = tid + 256 * i, row = g >> 3, qc = g & 7;
                uint4 sv;
                sv.x = f2tf32(av[i].x); sv.y = f2tf32(av[i].y);
                sv.z = f2tf32(av[i].z); sv.w = f2tf32(av[i].w);
                *(uint4*)&Anext[row * ST + qc * 4] = sv;
            }
            __syncthreads();
        }
    }

    #pragma unroll
    for (int mt = 0; mt < 2; mt++) {
        #pragma unroll
        for (int half = 0; half < 2; half++) {
            int r = bm + mw + mt * 16 + gid + half * 8;
            if (r >= M) continue;
            #pragma unroll
            for (int nt = 0; nt < 8; nt++) {
                int col = nw + nt * 8 + tig * 2;
                float2 o;
                o.x = acc[mt][nt][half * 2 + 0] + bias[col];
                o.y = acc[mt][nt][half * 2 + 1] + bias[col + 1];
                if (ex) {
                    float2 e = *(const float2*)(ex + (size_t)r * DD + col);
                    o.x += e.x; o.y += e.y;
                }
                if (C)   *(float2*)(C + (size_t)r * DD + col) = o;
                if (C16) *(__half2*)(C16 + (size_t)r * DD + col) = __float22half2_rn(o);
            }
        }
    }
}

// ---- CSR build ----
__global__ __launch_bounds__(256)
void hist_kernel(const int* __restrict__ dst_c, const int* __restrict__ dst_e,
                 int nC, int nTot)
{
    int i = blockIdx.x * 256 + threadIdx.x;
    if (i >= nTot) return;
    int* cnt;
    if (i < nC) cnt = &g_deg[dst_c[i]];
    else        cnt = &g_deg[PADN + dst_e[i - nC]];
    asm volatile("red.global.add.u32 [%0], %1;" :: "l"(cnt), "r"(1) : "memory");
}

// Fused exclusive scan over degrees -> row starts + cursors. One block per etype.
__global__ __launch_bounds__(1024)
void scan_fused_kernel(int N, int nEc, int nEe)
{
    const int et   = blockIdx.x;
    const int tid  = threadIdx.x;
    const int lane = tid & 31;
    const int wid  = tid >> 5;

    __shared__ int wt[32];
    __shared__ int tot_s;

    const int* deg = g_deg + (size_t)et * PADN;
    int*       rs  = g_rs  + (size_t)et * RSN;
    int*       cur = g_cur + (size_t)et * NN;

    int carry = 0;
    const int iters = (N + 4095) >> 12;   // 4096 elems per iter
    for (int it = 0; it < iters; it++) {
        int base = (it << 12) + tid * 4;
        int4 d = *(const int4*)(deg + base);
        int s = d.x + d.y + d.z + d.w;

        int incl = s;
        #pragma unroll
        for (int o = 1; o < 32; o <<= 1) {
            int t = __shfl_up_sync(0xffffffffu, incl, o);
            if (lane >= o) incl += t;
        }
        if (lane == 31) wt[wid] = incl;
        __syncthreads();
        if (wid == 0) {
            int v = wt[lane];
            int wi = v;
            #pragma unroll
            for (int o = 1; o < 32; o <<= 1) {
                int t = __shfl_up_sync(0xffffffffu, wi, o);
                if (lane >= o) wi += t;
            }
            wt[lane] = wi - v;               // exclusive warp base
            if (lane == 31) tot_s = wi;      // block total
        }
        __syncthreads();

        int p = carry + wt[wid] + incl - s;  // exclusive prefix of this thread's group
        if (base + 0 < N) { rs[base + 0] = p; cur[base + 0] = p; } p += d.x;
        if (base + 1 < N) { rs[base + 1] = p; cur[base + 1] = p; } p += d.y;
        if (base + 2 < N) { rs[base + 2] = p; cur[base + 2] = p; } p += d.z;
        if (base + 3 < N) { rs[base + 3] = p; cur[base + 3] = p; }

        carry += tot_s;
        __syncthreads();   // protect wt/tot_s before next iter
    }
    if (tid == 0) rs[N] = et ? nEe : nEc;
}

__global__ __launch_bounds__(256)
void place_kernel(const int* __restrict__ src_c, const int* __restrict__ dst_c,
                  const int* __restrict__ src_e, const int* __restrict__ dst_e,
                  int nC, int nTot)
{
    int i = blockIdx.x * 256 + threadIdx.x;
    if (i >= nTot) return;
    if (i < nC) {
        int d = dst_c[i];
        int p = atomicAdd(&g_cur[d], 1);
        g_csr[p] = src_c[i];
    } else {
        int e = i - nC;
        int d = dst_e[e];
        int p = atomicAdd(&g_cur[NN + d], 1);
        g_csr[NE + p] = src_e[e];
    }
}

// ---- Gather aggregation: one warp per node, fp16 rows (256B), fp32 accumulate ----
// Each lane owns 4 halves: uint2 (8B) load at half-offset lane*4; float4 store.
__global__ __launch_bounds__(256)
void aggregate_kernel(int N)
{
    int warp = (int)((blockIdx.x * (unsigned)blockDim.x + threadIdx.x) >> 5);
    int lane = threadIdx.x & 31;
    if (warp >= N) return;

    float acc[4];
    #pragma unroll
    for (int j = 0; j < 4; j++) acc[j] = 0.0f;

    #pragma unroll
    for (int et = 0; et < 2; et++) {
        const __half* Wh  = g_Wh16 + (size_t)et * NN * DD;
        const int*    csr = g_csr + (size_t)et * NE;
        int beg = __ldg(&g_rs[et * RSN + warp]);
        int end = __ldg(&g_rs[et * RSN + warp + 1]);
        int i = beg;
        for (; i + 1 < end; i += 2) {
            int s0 = __ldg(csr + i);
            int s1 = __ldg(csr + i + 1);
            uint2 r0 = __ldg((const uint2*)(Wh + (size_t)s0 * DD) + lane);
            uint2 r1 = __ldg((const uint2*)(Wh + (size_t)s1 * DD) + lane);
            float2 a0 = __half22float2(*(const __half2*)&r0.x);
            float2 b0 = __half22float2(*(const __half2*)&r0.y);
            float2 a1 = __half22float2(*(const __half2*)&r1.x);
            float2 b1 = __half22float2(*(const __half2*)&r1.y);
            acc[0] += a0.x + a1.x; acc[1] += a0.y + a1.y;
            acc[2] += b0.x + b1.x; acc[3] += b0.y + b1.y;
        }
        if (i < end) {
            int s0 = __ldg(csr + i);
            uint2 r0 = __ldg((const uint2*)(Wh + (size_t)s0 * DD) + lane);
            float2 a0 = __half22float2(*(const __half2*)&r0.x);
            float2 b0 = __half22float2(*(const __half2*)&r0.y);
            acc[0] += a0.x; acc[1] += a0.y;
            acc[2] += b0.x; acc[3] += b0.y;
        }
    }
    *((float4*)(g_h + (size_t)warp * DD) + lane) =
        make_float4(acc[0], acc[1], acc[2], acc[3]);
}

extern "C" void kernel_launch(void* const* d_in, const int* in_sizes, int n_in,
                              void* d_out, int out_size)
{
    const float* feats   = (const float*)d_in[0];
    const float* W_chem  = (const float*)d_in[1];
    const float* b_chem  = (const float*)d_in[2];
    const float* W_elec  = (const float*)d_in[3];
    const float* b_elec  = (const float*)d_in[4];
    const float* W_out   = (const float*)d_in[5];
    const float* b_out   = (const float*)d_in[6];
    const int*   src_ch  = (const int*)d_in[7];
    const int*   dst_ch  = (const int*)d_in[8];
    const int*   src_el  = (const int*)d_in[9];
    const int*   dst_el  = (const int*)d_in[10];
    float*       out     = (float*)d_out;

    const int M       = in_sizes[0] / DD;   // 50000
    const int nE_chem = in_sizes[7];
    const int nE_elec = in_sizes[9];
    const int nTot    = nE_chem + nE_elec;

    float  *wh_elec, *hbuf;
    __half *wh16;
    void   *degp;
    cudaGetSymbolAddress((void**)&wh_elec, g_Wh_elec);
    cudaGetSymbolAddress((void**)&wh16,    g_Wh16);
    cudaGetSymbolAddress((void**)&hbuf,    g_h);
    cudaGetSymbolAddress(&degp,            g_deg);

    cudaFuncSetAttribute(gemm_tf32_kernel,
                         cudaFuncAttributeMaxDynamicSharedMemorySize, SMEM_BYTES);

    const int mblocks = (M + BM - 1) / BM;

    // K1: dual GEMM — y==0: Wh_chem (fp16 only), y==1: Wh_elec (fp32 + fp16)
    gemm_tf32_kernel<<<dim3(mblocks, 2), 256, SMEM_BYTES>>>(
        feats,
        W_chem, b_chem, /*C0=*/nullptr, /*C16_0=*/wh16,
        W_elec, b_elec, /*C1=*/wh_elec, /*C16_1=*/wh16 + (size_t)NN * DD,
        /*extra=*/nullptr, M);

    // CSR build
    cudaMemsetAsync(degp, 0, 2 * PADN * sizeof(int));
    hist_kernel<<<(nTot + 255) / 256, 256>>>(dst_ch, dst_el, nE_chem, nTot);
    scan_fused_kernel<<<2, 1024>>>(M, nE_chem, nE_elec);
    place_kernel<<<(nTot + 255) / 256, 256>>>(src_ch, dst_ch, src_el, dst_el, nE_chem, nTot);

    // Gather aggregation (atomic-free, fp16 rows)
    aggregate_kernel<<<(M * 32 + 255) / 256, 256>>>(M);

    // K4: out = h @ W_out^T + b_out + Wh_elec (fp32 exact extra)
    gemm_tf32_kernel<<<dim3(mblocks, 1), 256, SMEM_BYTES>>>(
        hbuf,
        W_out, b_out, out, /*C16_0=*/nullptr,
        nullptr, nullptr, nullptr, nullptr,
        /*extra=*/wh_elec, M);
}

// round 7
// speedup vs baseline: 1.0197x; 1.0197x over previous
#include <cuda_runtime.h>
#include <cstdint>
#include <cstddef>

#define NN 50000
#define DD 128
#define BM 128
#define ST 36            // smem row stride (words): conflict-free fragment access
#define PADN 53248       // 13 * 4096, >= NN, int4-aligned scan coverage
#define RSN (NN + 1)
#define NE 500000

// ---- Scratch (allocation-free rule: device globals) ----
__device__ float g_Wh_chem[NN * DD];
__device__ float g_Wh_elec[NN * DD];
__device__ float g_h[NN * DD];
__device__ __align__(16) int g_deg[2 * PADN];  // per-etype dst degree (memset 0 each call)
__device__ int   g_rs[2 * RSN];                // CSR row starts
__device__ int   g_cur[2 * NN];                // placement cursors
__device__ int   g_csr[2 * NE];                // CSR src lists

__device__ __forceinline__ uint32_t f2tf32(float f) {
    uint32_t r;
    asm("cvt.rna.tf32.f32 %0, %1;" : "=r"(r) : "f"(f));
    return r;
}

__device__ __forceinline__ void mma_tf32(float c[4], const uint32_t a[4], const uint32_t b[2]) {
    asm volatile(
        "mma.sync.aligned.m16n8k8.row.col.f32.tf32.tf32.f32 "
        "{%0,%1,%2,%3}, {%4,%5,%6,%7}, {%8,%9}, {%0,%1,%2,%3};"
        : "+f"(c[0]), "+f"(c[1]), "+f"(c[2]), "+f"(c[3])
        : "r"(a[0]), "r"(a[1]), "r"(a[2]), "r"(a[3]), "r"(b[0]), "r"(b[1]));
}

// Dynamic smem: As[2][128][ST] | Ws[4][128][ST]
#define AS_WORDS (2 * 128 * ST)
#define WS_WORDS (4 * 128 * ST)
#define SMEM_BYTES ((AS_WORDS + WS_WORDS) * 4)

// C[M,128] = A[M,128] @ W^T + bias (+ extra). blockIdx.y selects param set.
__global__ __launch_bounds__(256, 2)
void gemm_tf32_kernel(const float* __restrict__ A,
                      const float* __restrict__ W0, const float* __restrict__ b0,
                      float* __restrict__ C0,
                      const float* __restrict__ W1, const float* __restrict__ b1,
                      float* __restrict__ C1,
                      const float* __restrict__ extra,
                      int M)
{
    extern __shared__ uint32_t smem[];
    uint32_t* As = smem;
    uint32_t* Ws = smem + AS_WORDS;

    const float* W    = W0;
    const float* bias = b0;
    float*       C    = C0;
    const float* ex   = extra;
    if (blockIdx.y == 1) { W = W1; bias = b1; C = C1; ex = nullptr; }

    const int tid  = threadIdx.x;
    const int lane = tid & 31;
    const int w    = tid >> 5;
    const int wm   = w & 3;
    const int wn   = w >> 2;
    const int mw   = wm * 32;
    const int nw   = wn * 64;
    const int gid  = lane >> 2;
    const int tig  = lane & 3;
    const int bm   = blockIdx.x * BM;

    // Prologue: all of W (128x128) into Ws, tf32, row-major
    #pragma unroll
    for (int i = 0; i < 16; i++) {
        int g   = tid + 256 * i;
        int c   = g >> 10;
        int row = (g >> 3) & 127;
        int qc  = g & 7;
        float4 vb = *(const float4*)(W + (size_t)row * DD + c * 32 + qc * 4);
        uint4 sv;
        sv.x = f2tf32(vb.x); sv.y = f2tf32(vb.y);
        sv.z = f2tf32(vb.z); sv.w = f2tf32(vb.w);
        *(uint4*)&Ws[(size_t)c * 128 * ST + row * ST + qc * 4] = sv;
    }

    float4 av[4];
    #pragma unroll
    for (int i = 0; i < 4; i++) {
        int g = tid + 256 * i, row = g >> 3, qc = g & 7, ar = bm + row;
        av[i] = make_float4(0.f, 0.f, 0.f, 0.f);
        if (ar < M) av[i] = *(const float4*)(A + (size_t)ar * DD + qc * 4);
    }
    #pragma unroll
    for (int i = 0; i < 4; i++) {
        int g = tid + 256 * i, row = g >> 3, qc = g & 7;
        uint4 sv;
        sv.x = f2tf32(av[i].x); sv.y = f2tf32(av[i].y);
        sv.z = f2tf32(av[i].z); sv.w = f2tf32(av[i].w);
        *(uint4*)&As[row * ST + qc * 4] = sv;
    }
    __syncthreads();

    float acc[2][8][4];
    #pragma unroll
    for (int mt = 0; mt < 2; mt++)
        #pragma unroll
        for (int nt = 0; nt < 8; nt++)
            #pragma unroll
            for (int q = 0; q < 4; q++) acc[mt][nt][q] = 0.0f;

    #pragma unroll
    for (int c = 0; c < 4; c++) {
        if (c < 3) {
            #pragma unroll
            for (int i = 0; i < 4; i++) {
                int g = tid + 256 * i, row = g >> 3, qc = g & 7, ar = bm + row;
                av[i] = make_float4(0.f, 0.f, 0.f, 0.f);
                if (ar < M) av[i] = *(const float4*)(A + (size_t)ar * DD + (c + 1) * 32 + qc * 4);
            }
        }
        const uint32_t* Ab = As + (size_t)(c & 1) * 128 * ST;
        const uint32_t* Wc = Ws + (size_t)c * 128 * ST;
        #pragma unroll
        for (int ks = 0; ks < 4; ks++) {
            const int k8 = ks * 8;
            uint32_t a[2][4], b[8][2];
            #pragma unroll
            for (int mt = 0; mt < 2; mt++) {
                int r0 = mw + mt * 16 + gid;
                a[mt][0] = Ab[r0 * ST + k8 + tig];
                a[mt][1] = Ab[(r0 + 8) * ST + k8 + tig];
                a[mt][2] = Ab[r0 * ST + k8 + tig + 4];
                a[mt][3] = Ab[(r0 + 8) * ST + k8 + tig + 4];
            }
            #pragma unroll
            for (int nt = 0; nt < 8; nt++) {
                int cc = nw + nt * 8 + gid;
                b[nt][0] = Wc[cc * ST + k8 + tig];
                b[nt][1] = Wc[cc * ST + k8 + tig + 4];
            }
            #pragma unroll
            for (int mt = 0; mt < 2; mt++)
                #pragma unroll
                for (int nt = 0; nt < 8; nt++)
                    mma_tf32(acc[mt][nt], a[mt], b[nt]);
        }
        if (c < 3) {
            uint32_t* Anext = As + (size_t)((c + 1) & 1) * 128 * ST;
            #pragma unroll
            for (int i = 0; i < 4; i++) {
                int g = tid + 256 * i, row = g >> 3, qc = g & 7;
                uint4 sv;
                sv.x = f2tf32(av[i].x); sv.y = f2tf32(av[i].y);
                sv.z = f2tf32(av[i].z); sv.w = f2tf32(av[i].w);
                *(uint4*)&Anext[row * ST + qc * 4] = sv;
            }
            __syncthreads();
        }
    }

    #pragma unroll
    for (int mt = 0; mt < 2; mt++) {
        #pragma unroll
        for (int half = 0; half < 2; half++) {
            int r = bm + mw + mt * 16 + gid + half * 8;
            if (r >= M) continue;
            #pragma unroll
            for (int nt = 0; nt < 8; nt++) {
                int col = nw + nt * 8 + tig * 2;
                float2 o;
                o.x = acc[mt][nt][half * 2 + 0] + bias[col];
                o.y = acc[mt][nt][half * 2 + 1] + bias[col + 1];
                if (ex) {
                    float2 e = *(const float2*)(ex + (size_t)r * DD + col);
                    o.x += e.x; o.y += e.y;
                }
                *(float2*)(C + (size_t)r * DD + col) = o;
            }
        }
    }
}

// ---- CSR build ----
__global__ __launch_bounds__(256)
void hist_kernel(const int* __restrict__ dst_c, const int* __restrict__ dst_e,
                 int nC, int nTot)
{
    int i = blockIdx.x * 256 + threadIdx.x;
    if (i >= nTot) return;
    int* cnt;
    if (i < nC) cnt = &g_deg[dst_c[i]];
    else        cnt = &g_deg[PADN + dst_e[i - nC]];
    asm volatile("red.global.add.u32 [%0], %1;" :: "l"(cnt), "r"(1) : "memory");
}

// Fused exclusive scan over degrees -> row starts + cursors. One block per etype.
__global__ __launch_bounds__(1024)
void scan_fused_kernel(int N, int nEc, int nEe)
{
    const int et   = blockIdx.x;
    const int tid  = threadIdx.x;
    const int lane = tid & 31;
    const int wid  = tid >> 5;

    __shared__ int wt[32];
    __shared__ int tot_s;

    const int* deg = g_deg + (size_t)et * PADN;
    int*       rs  = g_rs  + (size_t)et * RSN;
    int*       cur = g_cur + (size_t)et * NN;

    int carry = 0;
    const int iters = (N + 4095) >> 12;   // 4096 elems per iter
    for (int it = 0; it < iters; it++) {
        int base = (it << 12) + tid * 4;
        int4 d = *(const int4*)(deg + base);
        int s = d.x + d.y + d.z + d.w;

        int incl = s;
        #pragma unroll
        for (int o = 1; o < 32; o <<= 1) {
            int t = __shfl_up_sync(0xffffffffu, incl, o);
            if (lane >= o) incl += t;
        }
        if (lane == 31) wt[wid] = incl;
        __syncthreads();
        if (wid == 0) {
            int v = wt[lane];
            int wi = v;
            #pragma unroll
            for (int o = 1; o < 32; o <<= 1) {
                int t = __shfl_up_sync(0xffffffffu, wi, o);
                if (lane >= o) wi += t;
            }
            wt[lane] = wi - v;               // exclusive warp base
            if (lane == 31) tot_s = wi;      // block total
        }
        __syncthreads();

        int p = carry + wt[wid] + incl - s;
        if (base + 0 < N) { rs[base + 0] = p; cur[base + 0] = p; } p += d.x;
        if (base + 1 < N) { rs[base + 1] = p; cur[base + 1] = p; } p += d.y;
        if (base + 2 < N) { rs[base + 2] = p; cur[base + 2] = p; } p += d.z;
        if (base + 3 < N) { rs[base + 3] = p; cur[base + 3] = p; }

        carry += tot_s;
        __syncthreads();
    }
    if (tid == 0) rs[N] = et ? nEe : nEc;
}

__global__ __launch_bounds__(256)
void place_kernel(const int* __restrict__ src_c, const int* __restrict__ dst_c,
                  const int* __restrict__ src_e, const int* __restrict__ dst_e,
                  int nC, int nTot)
{
    int i = blockIdx.x * 256 + threadIdx.x;
    if (i >= nTot) return;
    if (i < nC) {
        int d = dst_c[i];
        int p = atomicAdd(&g_cur[d], 1);
        g_csr[p] = src_c[i];
    } else {
        int e = i - nC;
        int d = dst_e[e];
        int p = atomicAdd(&g_cur[NN + d], 1);
        g_csr[NE + p] = src_e[e];
    }
}

// ---- Gather aggregation: one warp per node, fp32 rows, MLP=4 ----
__global__ __launch_bounds__(256)
void aggregate_kernel(int N)
{
    int warp = (int)((blockIdx.x * (unsigned)blockDim.x + threadIdx.x) >> 5);
    int lane = threadIdx.x & 31;
    if (warp >= N) return;

    // Prefetch both etypes' bounds up front
    int beg0 = __ldg(&g_rs[warp]);
    int end0 = __ldg(&g_rs[warp + 1]);
    int beg1 = __ldg(&g_rs[RSN + warp]);
    int end1 = __ldg(&g_rs[RSN + warp + 1]);

    float4 acc = make_float4(0.f, 0.f, 0.f, 0.f);

    #pragma unroll
    for (int et = 0; et < 2; et++) {
        const float* Wh  = et ? g_Wh_elec : g_Wh_chem;
        const int*   csr = g_csr + (size_t)et * NE;
        int beg = et ? beg1 : beg0;
        int end = et ? end1 : end0;
        int i = beg;
        // 4-edge unrolled: 4 independent 512B row gathers in flight
        for (; i + 3 < end; i += 4) {
            int s0 = __ldg(csr + i);
            int s1 = __ldg(csr + i + 1);
            int s2 = __ldg(csr + i + 2);
            int s3 = __ldg(csr + i + 3);
            float4 v0 = __ldg((const float4*)(Wh + (size_t)s0 * DD) + lane);
            float4 v1 = __ldg((const float4*)(Wh + (size_t)s1 * DD) + lane);
            float4 v2 = __ldg((const float4*)(Wh + (size_t)s2 * DD) + lane);
            float4 v3 = __ldg((const float4*)(Wh + (size_t)s3 * DD) + lane);
            acc.x += (v0.x + v1.x) + (v2.x + v3.x);
            acc.y += (v0.y + v1.y) + (v2.y + v3.y);
            acc.z += (v0.z + v1.z) + (v2.z + v3.z);
            acc.w += (v0.w + v1.w) + (v2.w + v3.w);
        }
        for (; i < end; i++) {
            int s0 = __ldg(csr + i);
            float4 v0 = __ldg((const float4*)(Wh + (size_t)s0 * DD) + lane);
            acc.x += v0.x; acc.y += v0.y; acc.z += v0.z; acc.w += v0.w;
        }
    }
    *((float4*)(g_h + (size_t)warp * DD) + lane) = acc;
}

extern "C" void kernel_launch(void* const* d_in, const int* in_sizes, int n_in,
                              void* d_out, int out_size)
{
    const float* feats   = (const float*)d_in[0];
    const float* W_chem  = (const float*)d_in[1];
    const float* b_chem  = (const float*)d_in[2];
    const float* W_elec  = (const float*)d_in[3];
    const float* b_elec  = (const float*)d_in[4];
    const float* W_out   = (const float*)d_in[5];
    const float* b_out   = (const float*)d_in[6];
    const int*   src_ch  = (const int*)d_in[7];
    const int*   dst_ch  = (const int*)d_in[8];
    const int*   src_el  = (const int*)d_in[9];
    const int*   dst_el  = (const int*)d_in[10];
    float*       out     = (float*)d_out;

    const int M       = in_sizes[0] / DD;   // 50000
    const int nE_chem = in_sizes[7];
    const int nE_elec = in_sizes[9];
    const int nTot    = nE_chem + nE_elec;

    float *wh_chem, *wh_elec, *hbuf;
    void  *degp;
    cudaGetSymbolAddress((void**)&wh_chem, g_Wh_chem);
    cudaGetSymbolAddress((void**)&wh_elec, g_Wh_elec);
    cudaGetSymbolAddress((void**)&hbuf,    g_h);
    cudaGetSymbolAddress(&degp,            g_deg);

    cudaFuncSetAttribute(gemm_tf32_kernel,
                         cudaFuncAttributeMaxDynamicSharedMemorySize, SMEM_BYTES);

    const int mblocks = (M + BM - 1) / BM;

    // K1: dual GEMM — Wh_chem & Wh_elec (fp32)
    gemm_tf32_kernel<<<dim3(mblocks, 2), 256, SMEM_BYTES>>>(
        feats, W_chem, b_chem, wh_chem,
        W_elec, b_elec, wh_elec,
        /*extra=*/nullptr, M);

    // CSR build
    cudaMemsetAsync(degp, 0, 2 * PADN * sizeof(int));
    hist_kernel<<<(nTot + 255) / 256, 256>>>(dst_ch, dst_el, nE_chem, nTot);
    scan_fused_kernel<<<2, 1024>>>(M, nE_chem, nE_elec);
    place_kernel<<<(nTot + 255) / 256, 256>>>(src_ch, dst_ch, src_el, dst_el, nE_chem, nTot);

    // Gather aggregation (atomic-free, fp32 rows, MLP=4)
    aggregate_kernel<<<(M * 32 + 255) / 256, 256>>>(M);

    // K4: out = h @ W_out^T + b_out + Wh_elec
    gemm_tf32_kernel<<<dim3(mblocks, 1), 256, SMEM_BYTES>>>(
        hbuf, W_out, b_out, out,
        nullptr, nullptr, nullptr,
        /*extra=*/wh_elec, M);
}

// round 8
// speedup vs baseline: 1.2609x; 1.2365x over previous
#include <cuda_runtime.h>
#include <cstdint>
#include <cstddef>

#define NN 50000
#define DD 128
#define BM 128
#define ST 36            // smem row stride (words): conflict-free fragment access
#define CHUNK 512
#define NCHUNK 98        // ceil(50000/512)
#define PADN (NCHUNK * CHUNK)   // 50176
#define RSN (NN + 1)
#define NE 500000

// ---- Scratch (allocation-free rule: device globals) ----
__device__ float g_Wh_chem[NN * DD];
__device__ float g_Wh_elec[NN * DD];
__device__ float g_h[NN * DD];
__device__ int   g_deg[2 * PADN];     // per-etype dst degree (memset 0 each call)
__device__ int   g_local[2 * PADN];   // within-chunk exclusive scan
__device__ int   g_ctot[2 * NCHUNK];  // per-chunk totals
__device__ int   g_coff[2 * NCHUNK];  // scanned chunk offsets
__device__ int   g_rs[2 * RSN];       // CSR row starts
__device__ int   g_cur[2 * NN];       // placement cursors
__device__ int   g_csr[2 * NE];       // CSR src lists

__device__ __forceinline__ uint32_t f2tf32(float f) {
    uint32_t r;
    asm("cvt.rna.tf32.f32 %0, %1;" : "=r"(r) : "f"(f));
    return r;
}

__device__ __forceinline__ void mma_tf32(float c[4], const uint32_t a[4], const uint32_t b[2]) {
    asm volatile(
        "mma.sync.aligned.m16n8k8.row.col.f32.tf32.tf32.f32 "
        "{%0,%1,%2,%3}, {%4,%5,%6,%7}, {%8,%9}, {%0,%1,%2,%3};"
        : "+f"(c[0]), "+f"(c[1]), "+f"(c[2]), "+f"(c[3])
        : "r"(a[0]), "r"(a[1]), "r"(a[2]), "r"(a[3]), "r"(b[0]), "r"(b[1]));
}

// Dynamic smem: As[2][128][ST] | Ws[4][128][ST]
#define AS_WORDS (2 * 128 * ST)
#define WS_WORDS (4 * 128 * ST)
#define SMEM_BYTES ((AS_WORDS + WS_WORDS) * 4)

// C[M,128] = A[M,128] @ W^T + bias (+ extra). blockIdx.y selects param set.
__global__ __launch_bounds__(256, 2)
void gemm_tf32_kernel(const float* __restrict__ A,
                      const float* __restrict__ W0, const float* __restrict__ b0,
                      float* __restrict__ C0,
                      const float* __restrict__ W1, const float* __restrict__ b1,
                      float* __restrict__ C1,
                      const float* __restrict__ extra,
                      int M)
{
    extern __shared__ uint32_t smem[];
    uint32_t* As = smem;
    uint32_t* Ws = smem + AS_WORDS;

    const float* W    = W0;
    const float* bias = b0;
    float*       C    = C0;
    const float* ex   = extra;
    if (blockIdx.y == 1) { W = W1; bias = b1; C = C1; ex = nullptr; }

    const int tid  = threadIdx.x;
    const int lane = tid & 31;
    const int w    = tid >> 5;
    const int wm   = w & 3;
    const int wn   = w >> 2;
    const int mw   = wm * 32;
    const int nw   = wn * 64;
    const int gid  = lane >> 2;
    const int tig  = lane & 3;
    const int bm   = blockIdx.x * BM;

    // Prologue: all of W (128x128) into Ws, tf32, row-major
    #pragma unroll
    for (int i = 0; i < 16; i++) {
        int g   = tid + 256 * i;
        int c   = g >> 10;
        int row = (g >> 3) & 127;
        int qc  = g & 7;
        float4 vb = *(const float4*)(W + (size_t)row * DD + c * 32 + qc * 4);
        uint4 sv;
        sv.x = f2tf32(vb.x); sv.y = f2tf32(vb.y);
        sv.z = f2tf32(vb.z); sv.w = f2tf32(vb.w);
        *(uint4*)&Ws[(size_t)c * 128 * ST + row * ST + qc * 4] = sv;
    }

    float4 av[4];
    #pragma unroll
    for (int i = 0; i < 4; i++) {
        int g = tid + 256 * i, row = g >> 3, qc = g & 7, ar = bm + row;
        av[i] = make_float4(0.f, 0.f, 0.f, 0.f);
        if (ar < M) av[i] = *(const float4*)(A + (size_t)ar * DD + qc * 4);
    }
    #pragma unroll
    for (int i = 0; i < 4; i++) {
        int g = tid + 256 * i, row = g >> 3, qc = g & 7;
        uint4 sv;
        sv.x = f2tf32(av[i].x); sv.y = f2tf32(av[i].y);
        sv.z = f2tf32(av[i].z); sv.w = f2tf32(av[i].w);
        *(uint4*)&As[row * ST + qc * 4] = sv;
    }
    __syncthreads();

    float acc[2][8][4];
    #pragma unroll
    for (int mt = 0; mt < 2; mt++)
        #pragma unroll
        for (int nt = 0; nt < 8; nt++)
            #pragma unroll
            for (int q = 0; q < 4; q++) acc[mt][nt][q] = 0.0f;

    #pragma unroll
    for (int c = 0; c < 4; c++) {
        if (c < 3) {
            #pragma unroll
            for (int i = 0; i < 4; i++) {
                int g = tid + 256 * i, row = g >> 3, qc = g & 7, ar = bm + row;
                av[i] = make_float4(0.f, 0.f, 0.f, 0.f);
                if (ar < M) av[i] = *(const float4*)(A + (size_t)ar * DD + (c + 1) * 32 + qc * 4);
            }
        }
        const uint32_t* Ab = As + (size_t)(c & 1) * 128 * ST;
        const uint32_t* Wc = Ws + (size_t)c * 128 * ST;
        #pragma unroll
        for (int ks = 0; ks < 4; ks++) {
            const int k8 = ks * 8;
            uint32_t a[2][4], b[8][2];
            #pragma unroll
            for (int mt = 0; mt < 2; mt++) {
                int r0 = mw + mt * 16 + gid;
                a[mt][0] = Ab[r0 * ST + k8 + tig];
                a[mt][1] = Ab[(r0 + 8) * ST + k8 + tig];
                a[mt][2] = Ab[r0 * ST + k8 + tig + 4];
                a[mt][3] = Ab[(r0 + 8) * ST + k8 + tig + 4];
            }
            #pragma unroll
            for (int nt = 0; nt < 8; nt++) {
                int cc = nw + nt * 8 + gid;
                b[nt][0] = Wc[cc * ST + k8 + tig];
                b[nt][1] = Wc[cc * ST + k8 + tig + 4];
            }
            #pragma unroll
            for (int mt = 0; mt < 2; mt++)
                #pragma unroll
                for (int nt = 0; nt < 8; nt++)
                    mma_tf32(acc[mt][nt], a[mt], b[nt]);
        }
        if (c < 3) {
            uint32_t* Anext = As + (size_t)((c + 1) & 1) * 128 * ST;
            #pragma unroll
            for (int i = 0; i < 4; i++) {
                int g = tid + 256 * i, row = g >> 3, qc = g & 7;
                uint4 sv;
                sv.x = f2tf32(av[i].x); sv.y = f2tf32(av[i].y);
                sv.z = f2tf32(av[i].z); sv.w = f2tf32(av[i].w);
                *(uint4*)&Anext[row * ST + qc * 4] = sv;
            }
            __syncthreads();
        }
    }

    #pragma unroll
    for (int mt = 0; mt < 2; mt++) {
        #pragma unroll
        for (int half = 0; half < 2; half++) {
            int r = bm + mw + mt * 16 + gid + half * 8;
            if (r >= M) continue;
            #pragma unroll
            for (int nt = 0; nt < 8; nt++) {
                int col = nw + nt * 8 + tig * 2;
                float2 o;
                o.x = acc[mt][nt][half * 2 + 0] + bias[col];
                o.y = acc[mt][nt][half * 2 + 1] + bias[col + 1];
                if (ex) {
                    float2 e = *(const float2*)(ex + (size_t)r * DD + col);
                    o.x += e.x; o.y += e.y;
                }
                *(float2*)(C + (size_t)r * DD + col) = o;
            }
        }
    }
}

// ---- CSR build (R4-proven chain) ----
__global__ __launch_bounds__(256)
void hist_kernel(const int* __restrict__ dst_c, const int* __restrict__ dst_e,
                 int nC, int nTot)
{
    int i = blockIdx.x * 256 + threadIdx.x;
    if (i >= nTot) return;
    int* cnt;
    if (i < nC) cnt = &g_deg[dst_c[i]];
    else        cnt = &g_deg[PADN + dst_e[i - nC]];
    asm volatile("red.global.add.u32 [%0], %1;" :: "l"(cnt), "r"(1) : "memory");
}

__global__ __launch_bounds__(512)
void scan_chunks_kernel(int N)
{
    const int et   = blockIdx.y;
    const int lane = threadIdx.x & 31;
    const int wid  = threadIdx.x >> 5;
    int n = blockIdx.x * CHUNK + threadIdx.x;
    int d = (n < N) ? g_deg[et * PADN + n] : 0;

    int incl = d;
    #pragma unroll
    for (int o = 1; o < 32; o <<= 1) {
        int t = __shfl_up_sync(0xffffffffu, incl, o);
        if (lane >= o) incl += t;
    }
    __shared__ int wtot[16];
    if (lane == 31) wtot[wid] = incl;
    __syncthreads();
    if (wid == 0) {
        int v = (lane < 16) ? wtot[lane] : 0;
        int wi = v;
        #pragma unroll
        for (int o = 1; o < 16; o <<= 1) {
            int t = __shfl_up_sync(0xffffffffu, wi, o);
            if (lane >= o) wi += t;
        }
        if (lane < 16) wtot[lane] = wi - v;   // exclusive warp bases
    }
    __syncthreads();
    int base = wtot[wid];
    if (n < N) g_local[et * PADN + n] = base + incl - d;
    if (wid == 15 && lane == 31) g_ctot[et * NCHUNK + blockIdx.x] = base + incl;
}

__global__ __launch_bounds__(64)
void scan_totals_kernel()
{
    const int et   = threadIdx.x >> 5;
    const int lane = threadIdx.x & 31;
    int carry = 0;
    for (int it = 0; it < (NCHUNK + 31) / 32; it++) {
        int idx = it * 32 + lane;
        int v = (idx < NCHUNK) ? g_ctot[et * NCHUNK + idx] : 0;
        int incl = v;
        #pragma unroll
        for (int o = 1; o < 32; o <<= 1) {
            int t = __shfl_up_sync(0xffffffffu, incl, o);
            if (lane >= o) incl += t;
        }
        if (idx < NCHUNK) g_coff[et * NCHUNK + idx] = carry + incl - v;
        carry += __shfl_sync(0xffffffffu, incl, 31);
    }
}

__global__ __launch_bounds__(256)
void rowstart_kernel(int N, int nEc, int nEe)
{
    int n = blockIdx.x * 256 + threadIdx.x;
    if (n > N) return;
    #pragma unroll
    for (int et = 0; et < 2; et++) {
        int v;
        if (n == N) v = et ? nEe : nEc;
        else v = g_coff[et * NCHUNK + (n >> 9)] + g_local[et * PADN + n];
        g_rs[et * RSN + n] = v;
        if (n < N) g_cur[et * NN + n] = v;
    }
}

// 2 edges per thread: MLP=2 on the index->atomic->scatter chains.
__global__ __launch_bounds__(256)
void place_kernel(const int* __restrict__ src_c, const int* __restrict__ dst_c,
                  const int* __restrict__ src_e, const int* __restrict__ dst_e,
                  int nC, int nE_)
{
    int t = blockIdx.x * 256 + threadIdx.x;
    int nPairC = (nC + 1) >> 1;
    int nPairE = (nE_ + 1) >> 1;
    if (t < nPairC) {
        int e0 = 2 * t, e1 = 2 * t + 1;
        int d0 = dst_c[e0];
        int s0 = src_c[e0];
        int d1 = -1, s1 = 0;
        if (e1 < nC) { d1 = dst_c[e1]; s1 = src_c[e1]; }
        int p0 = atomicAdd(&g_cur[d0], 1);
        int p1 = (d1 >= 0) ? atomicAdd(&g_cur[d1], 1) : -1;
        g_csr[p0] = s0;
        if (p1 >= 0) g_csr[p1] = s1;
    } else if (t < nPairC + nPairE) {
        int u = t - nPairC;
        int e0 = 2 * u, e1 = 2 * u + 1;
        int d0 = dst_e[e0];
        int s0 = src_e[e0];
        int d1 = -1, s1 = 0;
        if (e1 < nE_) { d1 = dst_e[e1]; s1 = src_e[e1]; }
        int p0 = atomicAdd(&g_cur[NN + d0], 1);
        int p1 = (d1 >= 0) ? atomicAdd(&g_cur[NN + d1], 1) : -1;
        g_csr[NE + p0] = s0;
        if (p1 >= 0) g_csr[NE + p1] = s1;
    }
}

// ---- Gather aggregation: one warp per node, fp32 rows, MLP=4 ----
__global__ __launch_bounds__(256)
void aggregate_kernel(int N)
{
    int warp = (int)((blockIdx.x * (unsigned)blockDim.x + threadIdx.x) >> 5);
    int lane = threadIdx.x & 31;
    if (warp >= N) return;

    int beg0 = __ldg(&g_rs[warp]);
    int end0 = __ldg(&g_rs[warp + 1]);
    int beg1 = __ldg(&g_rs[RSN + warp]);
    int end1 = __ldg(&g_rs[RSN + warp + 1]);

    float4 acc = make_float4(0.f, 0.f, 0.f, 0.f);

    #pragma unroll
    for (int et = 0; et < 2; et++) {
        const float* Wh  = et ? g_Wh_elec : g_Wh_chem;
        const int*   csr = g_csr + (size_t)et * NE;
        int beg = et ? beg1 : beg0;
        int end = et ? end1 : end0;
        int i = beg;
        for (; i + 3 < end; i += 4) {
            int s0 = __ldg(csr + i);
            int s1 = __ldg(csr + i + 1);
            int s2 = __ldg(csr + i + 2);
            int s3 = __ldg(csr + i + 3);
            float4 v0 = __ldg((const float4*)(Wh + (size_t)s0 * DD) + lane);
            float4 v1 = __ldg((const float4*)(Wh + (size_t)s1 * DD) + lane);
            float4 v2 = __ldg((const float4*)(Wh + (size_t)s2 * DD) + lane);
            float4 v3 = __ldg((const float4*)(Wh + (size_t)s3 * DD) + lane);
            acc.x += (v0.x + v1.x) + (v2.x + v3.x);
            acc.y += (v0.y + v1.y) + (v2.y + v3.y);
            acc.z += (v0.z + v1.z) + (v2.z + v3.z);
            acc.w += (v0.w + v1.w) + (v2.w + v3.w);
        }
        for (; i < end; i++) {
            int s0 = __ldg(csr + i);
            float4 v0 = __ldg((const float4*)(Wh + (size_t)s0 * DD) + lane);
            acc.x += v0.x; acc.y += v0.y; acc.z += v0.z; acc.w += v0.w;
        }
    }
    *((float4*)(g_h + (size_t)warp * DD) + lane) = acc;
}

extern "C" void kernel_launch(void* const* d_in, const int* in_sizes, int n_in,
                              void* d_out, int out_size)
{
    const float* feats   = (const float*)d_in[0];
    const float* W_chem  = (const float*)d_in[1];
    const float* b_chem  = (const float*)d_in[2];
    const float* W_elec  = (const float*)d_in[3];
    const float* b_elec  = (const float*)d_in[4];
    const float* W_out   = (const float*)d_in[5];
    const float* b_out   = (const float*)d_in[6];
    const int*   src_ch  = (const int*)d_in[7];
    const int*   dst_ch  = (const int*)d_in[8];
    const int*   src_el  = (const int*)d_in[9];
    const int*   dst_el  = (const int*)d_in[10];
    float*       out     = (float*)d_out;

    const int M       = in_sizes[0] / DD;   // 50000
    const int nE_chem = in_sizes[7];
    const int nE_elec = in_sizes[9];
    const int nTot    = nE_chem + nE_elec;

    float *wh_chem, *wh_elec, *hbuf;
    void  *degp;
    cudaGetSymbolAddress((void**)&wh_chem, g_Wh_chem);
    cudaGetSymbolAddress((void**)&wh_elec, g_Wh_elec);
    cudaGetSymbolAddress((void**)&hbuf,    g_h);
    cudaGetSymbolAddress(&degp,            g_deg);

    cudaFuncSetAttribute(gemm_tf32_kernel,
                         cudaFuncAttributeMaxDynamicSharedMemorySize, SMEM_BYTES);

    const int mblocks = (M + BM - 1) / BM;

    // K1: dual GEMM — Wh_chem & Wh_elec (fp32)
    gemm_tf32_kernel<<<dim3(mblocks, 2), 256, SMEM_BYTES>>>(
        feats, W_chem, b_chem, wh_chem,
        W_elec, b_elec, wh_elec,
        /*extra=*/nullptr, M);

    // CSR build (R4-proven chain)
    cudaMemsetAsync(degp, 0, 2 * PADN * sizeof(int));
    hist_kernel<<<(nTot + 255) / 256, 256>>>(dst_ch, dst_el, nE_chem, nTot);
    scan_chunks_kernel<<<dim3(NCHUNK, 2), 512>>>(M);
    scan_totals_kernel<<<1, 64>>>();
    rowstart_kernel<<<(M + 256) / 256, 256>>>(M, nE_chem, nE_elec);
    {
        int nPair = ((nE_chem + 1) >> 1) + ((nE_elec + 1) >> 1);
        place_kernel<<<(nPair + 255) / 256, 256>>>(src_ch, dst_ch, src_el, dst_el,
                                                   nE_chem, nE_elec);
    }

    // Gather aggregation (atomic-free, fp32 rows, MLP=4)
    aggregate_kernel<<<(M * 32 + 255) / 256, 256>>>(M);

    // K4: out = h @ W_out^T + b_out + Wh_elec
    gemm_tf32_kernel<<<dim3(mblocks, 1), 256, SMEM_BYTES>>>(
        hbuf, W_out, b_out, out,
        nullptr, nullptr, nullptr,
        /*extra=*/wh_elec, M);
}

// round 9
// speedup vs baseline: 1.3034x; 1.0337x over previous
#include <cuda_runtime.h>
#include <cstdint>
#include <cstddef>

#define NN 50000
#define DD 128
#define BM 128
#define ST 36            // smem row stride (words): conflict-free fragment access
#define CHUNK 512
#define NCHUNK 98        // ceil(50000/512)
#define PADN (NCHUNK * CHUNK)   // 50176
#define RSN (NN + 1)
#define NE 500000

// ---- Scratch (allocation-free rule: device globals) ----
__device__ float g_Wh_chem[NN * DD];
__device__ float g_Wh_elec[NN * DD];
__device__ float g_h[NN * DD];
__device__ int   g_deg[2 * PADN];     // per-etype dst degree (memset 0 each call)
__device__ int   g_local[2 * PADN];   // within-chunk exclusive scan
__device__ int   g_ctot[2 * NCHUNK];  // per-chunk totals
__device__ int   g_coff[2 * NCHUNK];  // scanned chunk offsets
__device__ int   g_rs[2 * RSN];       // CSR row starts
__device__ int   g_cur[2 * NN];       // placement cursors
__device__ int   g_csr[2 * NE];       // CSR src lists

__device__ __forceinline__ uint32_t f2tf32(float f) {
    uint32_t r;
    asm("cvt.rna.tf32.f32 %0, %1;" : "=r"(r) : "f"(f));
    return r;
}

__device__ __forceinline__ void mma_tf32(float c[4], const uint32_t a[4], const uint32_t b[2]) {
    asm volatile(
        "mma.sync.aligned.m16n8k8.row.col.f32.tf32.tf32.f32 "
        "{%0,%1,%2,%3}, {%4,%5,%6,%7}, {%8,%9}, {%0,%1,%2,%3};"
        : "+f"(c[0]), "+f"(c[1]), "+f"(c[2]), "+f"(c[3])
        : "r"(a[0]), "r"(a[1]), "r"(a[2]), "r"(a[3]), "r"(b[0]), "r"(b[1]));
}

// Dynamic smem: As[2][128][ST] | Ws[4][128][ST]
#define AS_WORDS (2 * 128 * ST)
#define WS_WORDS (4 * 128 * ST)
#define SMEM_BYTES ((AS_WORDS + WS_WORDS) * 4)

// C[M,128] = A[M,128] @ W^T + bias (+ extra). blockIdx.y selects param set.
__global__ __launch_bounds__(256, 2)
void gemm_tf32_kernel(const float* __restrict__ A,
                      const float* __restrict__ W0, const float* __restrict__ b0,
                      float* __restrict__ C0,
                      const float* __restrict__ W1, const float* __restrict__ b1,
                      float* __restrict__ C1,
                      const float* __restrict__ extra,
                      int M)
{
    extern __shared__ uint32_t smem[];
    uint32_t* As = smem;
    uint32_t* Ws = smem + AS_WORDS;

    const float* W    = W0;
    const float* bias = b0;
    float*       C    = C0;
    const float* ex   = extra;
    if (blockIdx.y == 1) { W = W1; bias = b1; C = C1; ex = nullptr; }

    const int tid  = threadIdx.x;
    const int lane = tid & 31;
    const int w    = tid >> 5;
    const int wm   = w & 3;
    const int wn   = w >> 2;
    const int mw   = wm * 32;
    const int nw   = wn * 64;
    const int gid  = lane >> 2;
    const int tig  = lane & 3;
    const int bm   = blockIdx.x * BM;

    // Prologue: all of W (128x128) into Ws, tf32, row-major
    #pragma unroll
    for (int i = 0; i < 16; i++) {
        int g   = tid + 256 * i;
        int c   = g >> 10;
        int row = (g >> 3) & 127;
        int qc  = g & 7;
        float4 vb = *(const float4*)(W + (size_t)row * DD + c * 32 + qc * 4);
        uint4 sv;
        sv.x = f2tf32(vb.x); sv.y = f2tf32(vb.y);
        sv.z = f2tf32(vb.z); sv.w = f2tf32(vb.w);
        *(uint4*)&Ws[(size_t)c * 128 * ST + row * ST + qc * 4] = sv;
    }

    float4 av[4];
    #pragma unroll
    for (int i = 0; i < 4; i++) {
        int g = tid + 256 * i, row = g >> 3, qc = g & 7, ar = bm + row;
        av[i] = make_float4(0.f, 0.f, 0.f, 0.f);
        if (ar < M) av[i] = *(const float4*)(A + (size_t)ar * DD + qc * 4);
    }
    #pragma unroll
    for (int i = 0; i < 4; i++) {
        int g = tid + 256 * i, row = g >> 3, qc = g & 7;
        uint4 sv;
        sv.x = f2tf32(av[i].x); sv.y = f2tf32(av[i].y);
        sv.z = f2tf32(av[i].z); sv.w = f2tf32(av[i].w);
        *(uint4*)&As[row * ST + qc * 4] = sv;
    }
    __syncthreads();

    float acc[2][8][4];
    #pragma unroll
    for (int mt = 0; mt < 2; mt++)
        #pragma unroll
        for (int nt = 0; nt < 8; nt++)
            #pragma unroll
            for (int q = 0; q < 4; q++) acc[mt][nt][q] = 0.0f;

    #pragma unroll
    for (int c = 0; c < 4; c++) {
        if (c < 3) {
            #pragma unroll
            for (int i = 0; i < 4; i++) {
                int g = tid + 256 * i, row = g >> 3, qc = g & 7, ar = bm + row;
                av[i] = make_float4(0.f, 0.f, 0.f, 0.f);
                if (ar < M) av[i] = *(const float4*)(A + (size_t)ar * DD + (c + 1) * 32 + qc * 4);
            }
        }
        const uint32_t* Ab = As + (size_t)(c & 1) * 128 * ST;
        const uint32_t* Wc = Ws + (size_t)c * 128 * ST;
        #pragma unroll
        for (int ks = 0; ks < 4; ks++) {
            const int k8 = ks * 8;
            uint32_t a[2][4], b[8][2];
            #pragma unroll
            for (int mt = 0; mt < 2; mt++) {
                int r0 = mw + mt * 16 + gid;
                a[mt][0] = Ab[r0 * ST + k8 + tig];
                a[mt][1] = Ab[(r0 + 8) * ST + k8 + tig];
                a[mt][2] = Ab[r0 * ST + k8 + tig + 4];
                a[mt][3] = Ab[(r0 + 8) * ST + k8 + tig + 4];
            }
            #pragma unroll
            for (int nt = 0; nt < 8; nt++) {
                int cc = nw + nt * 8 + gid;
                b[nt][0] = Wc[cc * ST + k8 + tig];
                b[nt][1] = Wc[cc * ST + k8 + tig + 4];
            }
            #pragma unroll
            for (int mt = 0; mt < 2; mt++)
                #pragma unroll
                for (int nt = 0; nt < 8; nt++)
                    mma_tf32(acc[mt][nt], a[mt], b[nt]);
        }
        if (c < 3) {
            uint32_t* Anext = As + (size_t)((c + 1) & 1) * 128 * ST;
            #pragma unroll
            for (int i = 0; i < 4; i++) {
                int g = tid + 256 * i, row = g >> 3, qc = g & 7;
                uint4 sv;
                sv.x = f2tf32(av[i].x); sv.y = f2tf32(av[i].y);
                sv.z = f2tf32(av[i].z); sv.w = f2tf32(av[i].w);
                *(uint4*)&Anext[row * ST + qc * 4] = sv;
            }
            __syncthreads();
        }
    }

    #pragma unroll
    for (int mt = 0; mt < 2; mt++) {
        #pragma unroll
        for (int half = 0; half < 2; half++) {
            int r = bm + mw + mt * 16 + gid + half * 8;
            if (r >= M) continue;
            #pragma unroll
            for (int nt = 0; nt < 8; nt++) {
                int col = nw + nt * 8 + tig * 2;
                float2 o;
                o.x = acc[mt][nt][half * 2 + 0] + bias[col];
                o.y = acc[mt][nt][half * 2 + 1] + bias[col + 1];
                if (ex) {
                    float2 e = *(const float2*)(ex + (size_t)r * DD + col);
                    o.x += e.x; o.y += e.y;
                }
                *(float2*)(C + (size_t)r * DD + col) = o;
            }
        }
    }
}

// ---- CSR build ----
__global__ __launch_bounds__(256)
void hist_kernel(const int* __restrict__ dst_c, const int* __restrict__ dst_e,
                 int nC, int nTot)
{
    int i = blockIdx.x * 256 + threadIdx.x;
    if (i >= nTot) return;
    int* cnt;
    if (i < nC) cnt = &g_deg[dst_c[i]];
    else        cnt = &g_deg[PADN + dst_e[i - nC]];
    asm volatile("red.global.add.u32 [%0], %1;" :: "l"(cnt), "r"(1) : "memory");
}

__global__ __launch_bounds__(512)
void scan_chunks_kernel(int N)
{
    const int et   = blockIdx.y;
    const int lane = threadIdx.x & 31;
    const int wid  = threadIdx.x >> 5;
    int n = blockIdx.x * CHUNK + threadIdx.x;
    int d = (n < N) ? g_deg[et * PADN + n] : 0;

    int incl = d;
    #pragma unroll
    for (int o = 1; o < 32; o <<= 1) {
        int t = __shfl_up_sync(0xffffffffu, incl, o);
        if (lane >= o) incl += t;
    }
    __shared__ int wtot[16];
    if (lane == 31) wtot[wid] = incl;
    __syncthreads();
    if (wid == 0) {
        int v = (lane < 16) ? wtot[lane] : 0;
        int wi = v;
        #pragma unroll
        for (int o = 1; o < 16; o <<= 1) {
            int t = __shfl_up_sync(0xffffffffu, wi, o);
            if (lane >= o) wi += t;
        }
        if (lane < 16) wtot[lane] = wi - v;   // exclusive warp bases
    }
    __syncthreads();
    int base = wtot[wid];
    if (n < N) g_local[et * PADN + n] = base + incl - d;
    if (wid == 15 && lane == 31) g_ctot[et * NCHUNK + blockIdx.x] = base + incl;
}

__global__ __launch_bounds__(64)
void scan_totals_kernel()
{
    const int et   = threadIdx.x >> 5;
    const int lane = threadIdx.x & 31;
    int carry = 0;
    for (int it = 0; it < (NCHUNK + 31) / 32; it++) {
        int idx = it * 32 + lane;
        int v = (idx < NCHUNK) ? g_ctot[et * NCHUNK + idx] : 0;
        int incl = v;
        #pragma unroll
        for (int o = 1; o < 32; o <<= 1) {
            int t = __shfl_up_sync(0xffffffffu, incl, o);
            if (lane >= o) incl += t;
        }
        if (idx < NCHUNK) g_coff[et * NCHUNK + idx] = carry + incl - v;
        carry += __shfl_sync(0xffffffffu, incl, 31);
    }
}

__global__ __launch_bounds__(256)
void rowstart_kernel(int N, int nEc, int nEe)
{
    int n = blockIdx.x * 256 + threadIdx.x;
    if (n > N) return;
    #pragma unroll
    for (int et = 0; et < 2; et++) {
        int v;
        if (n == N) v = et ? nEe : nEc;
        else v = g_coff[et * NCHUNK + (n >> 9)] + g_local[et * PADN + n];
        g_rs[et * RSN + n] = v;
        if (n < N) g_cur[et * NN + n] = v;
    }
}

// 2 edges per thread: MLP=2 on the index->atomic->scatter chains.
__global__ __launch_bounds__(256)
void place_kernel(const int* __restrict__ src_c, const int* __restrict__ dst_c,
                  const int* __restrict__ src_e, const int* __restrict__ dst_e,
                  int nC, int nE_)
{
    int t = blockIdx.x * 256 + threadIdx.x;
    int nPairC = (nC + 1) >> 1;
    int nPairE = (nE_ + 1) >> 1;
    if (t < nPairC) {
        int e0 = 2 * t, e1 = 2 * t + 1;
        int d0 = dst_c[e0];
        int s0 = src_c[e0];
        int d1 = -1, s1 = 0;
        if (e1 < nC) { d1 = dst_c[e1]; s1 = src_c[e1]; }
        int p0 = atomicAdd(&g_cur[d0], 1);
        int p1 = (d1 >= 0) ? atomicAdd(&g_cur[d1], 1) : -1;
        g_csr[p0] = s0;
        if (p1 >= 0) g_csr[p1] = s1;
    } else if (t < nPairC + nPairE) {
        int u = t - nPairC;
        int e0 = 2 * u, e1 = 2 * u + 1;
        int d0 = dst_e[e0];
        int s0 = src_e[e0];
        int d1 = -1, s1 = 0;
        if (e1 < nE_) { d1 = dst_e[e1]; s1 = src_e[e1]; }
        int p0 = atomicAdd(&g_cur[NN + d0], 1);
        int p1 = (d1 >= 0) ? atomicAdd(&g_cur[NN + d1], 1) : -1;
        g_csr[NE + p0] = s0;
        if (p1 >= 0) g_csr[NE + p1] = s1;
    }
}

// ---- Gather aggregation: one warp per node, fp32 rows, MLP=4 ----
__global__ __launch_bounds__(256)
void aggregate_kernel(int N)
{
    int warp = (int)((blockIdx.x * (unsigned)blockDim.x + threadIdx.x) >> 5);
    int lane = threadIdx.x & 31;
    if (warp >= N) return;

    int beg0 = __ldg(&g_rs[warp]);
    int end0 = __ldg(&g_rs[warp + 1]);
    int beg1 = __ldg(&g_rs[RSN + warp]);
    int end1 = __ldg(&g_rs[RSN + warp + 1]);

    float4 acc = make_float4(0.f, 0.f, 0.f, 0.f);

    #pragma unroll
    for (int et = 0; et < 2; et++) {
        const float* Wh  = et ? g_Wh_elec : g_Wh_chem;
        const int*   csr = g_csr + (size_t)et * NE;
        int beg = et ? beg1 : beg0;
        int end = et ? end1 : end0;
        int i = beg;
        for (; i + 3 < end; i += 4) {
            int s0 = __ldg(csr + i);
            int s1 = __ldg(csr + i + 1);
            int s2 = __ldg(csr + i + 2);
            int s3 = __ldg(csr + i + 3);
            float4 v0 = __ldg((const float4*)(Wh + (size_t)s0 * DD) + lane);
            float4 v1 = __ldg((const float4*)(Wh + (size_t)s1 * DD) + lane);
            float4 v2 = __ldg((const float4*)(Wh + (size_t)s2 * DD) + lane);
            float4 v3 = __ldg((const float4*)(Wh + (size_t)s3 * DD) + lane);
            acc.x += (v0.x + v1.x) + (v2.x + v3.x);
            acc.y += (v0.y + v1.y) + (v2.y + v3.y);
            acc.z += (v0.z + v1.z) + (v2.z + v3.z);
            acc.w += (v0.w + v1.w) + (v2.w + v3.w);
        }
        for (; i < end; i++) {
            int s0 = __ldg(csr + i);
            float4 v0 = __ldg((const float4*)(Wh + (size_t)s0 * DD) + lane);
            acc.x += v0.x; acc.y += v0.y; acc.z += v0.z; acc.w += v0.w;
        }
    }
    *((float4*)(g_h + (size_t)warp * DD) + lane) = acc;
}

extern "C" void kernel_launch(void* const* d_in, const int* in_sizes, int n_in,
                              void* d_out, int out_size)
{
    const float* feats   = (const float*)d_in[0];
    const float* W_chem  = (const float*)d_in[1];
    const float* b_chem  = (const float*)d_in[2];
    const float* W_elec  = (const float*)d_in[3];
    const float* b_elec  = (const float*)d_in[4];
    const float* W_out   = (const float*)d_in[5];
    const float* b_out   = (const float*)d_in[6];
    const int*   src_ch  = (const int*)d_in[7];
    const int*   dst_ch  = (const int*)d_in[8];
    const int*   src_el  = (const int*)d_in[9];
    const int*   dst_el  = (const int*)d_in[10];
    float*       out     = (float*)d_out;

    const int M       = in_sizes[0] / DD;   // 50000
    const int nE_chem = in_sizes[7];
    const int nE_elec = in_sizes[9];
    const int nTot    = nE_chem + nE_elec;

    float *wh_chem, *wh_elec, *hbuf;
    void  *degp;
    cudaGetSymbolAddress((void**)&wh_chem, g_Wh_chem);
    cudaGetSymbolAddress((void**)&wh_elec, g_Wh_elec);
    cudaGetSymbolAddress((void**)&hbuf,    g_h);
    cudaGetSymbolAddress(&degp,            g_deg);

    cudaFuncSetAttribute(gemm_tf32_kernel,
                         cudaFuncAttributeMaxDynamicSharedMemorySize, SMEM_BYTES);

    // Side stream + fork/join events for capturing parallel branches.
    // Host-side resources only (no device memory); created once, outside capture
    // (the harness's correctness call precedes graph capture). Work per call is
    // identical and deterministic.
    static cudaStream_t s1 = nullptr;
    static cudaEvent_t  evFork = nullptr, evJoin = nullptr;
    if (s1 == nullptr) {
        cudaStreamCreateWithFlags(&s1, cudaStreamNonBlocking);
        cudaEventCreateWithFlags(&evFork, cudaEventDisableTiming);
        cudaEventCreateWithFlags(&evJoin, cudaEventDisableTiming);
    }

    const int mblocks = (M + BM - 1) / BM;

    // Fork: s1 branches off the main (captured) stream.
    cudaEventRecord(evFork, 0);
    cudaStreamWaitEvent(s1, evFork, 0);

    // Branch A (main stream): K1 dual GEMM — Wh_chem & Wh_elec (fp32)
    gemm_tf32_kernel<<<dim3(mblocks, 2), 256, SMEM_BYTES>>>(
        feats, W_chem, b_chem, wh_chem,
        W_elec, b_elec, wh_elec,
        /*extra=*/nullptr, M);

    // Branch B (s1): CSR build — independent of K1 (uses only edge indices)
    cudaMemsetAsync(degp, 0, 2 * PADN * sizeof(int), s1);
    hist_kernel<<<(nTot + 255) / 256, 256, 0, s1>>>(dst_ch, dst_el, nE_chem, nTot);
    scan_chunks_kernel<<<dim3(NCHUNK, 2), 512, 0, s1>>>(M);
    scan_totals_kernel<<<1, 64, 0, s1>>>();
    rowstart_kernel<<<(M + 256) / 256, 256, 0, s1>>>(M, nE_chem, nE_elec);
    {
        int nPair = ((nE_chem + 1) >> 1) + ((nE_elec + 1) >> 1);
        place_kernel<<<(nPair + 255) / 256, 256, 0, s1>>>(src_ch, dst_ch, src_el, dst_el,
                                                          nE_chem, nE_elec);
    }

    // Join: main stream waits for CSR build before aggregation.
    cudaEventRecord(evJoin, s1);
    cudaStreamWaitEvent(0, evJoin, 0);

    // Gather aggregation (needs K1 results + CSR)
    aggregate_kernel<<<(M * 32 + 255) / 256, 256>>>(M);

    // K4: out = h @ W_out^T + b_out + Wh_elec
    gemm_tf32_kernel<<<dim3(mblocks, 1), 256, SMEM_BYTES>>>(
        hbuf, W_out, b_out, out,
        nullptr, nullptr, nullptr,
        /*extra=*/wh_elec, M);
}